// round 2
// baseline (speedup 1.0000x reference)
#include <cuda_runtime.h>
#include <math.h>

#define N_LEAVES 262144
#define HID 128

// Ping-pong hidden-state buffers (static __device__ = allocation-guard safe).
__device__ float g_bufA[(size_t)N_LEAVES * HID];        // 128 MB : H0, H2, H4, ...
__device__ float g_bufB[(size_t)(N_LEAVES / 2) * HID];  //  64 MB : H1, H3, ...
__device__ float g_Wcat[256 * HID];                     // vstack(W_l, W_r)
__device__ float g_bsum[HID];                           // b_l + b_r

// Build Wcat and bsum once per launch sequence.
__global__ void prep_kernel(const float* __restrict__ W_l, const float* __restrict__ b_l,
                            const float* __restrict__ W_r, const float* __restrict__ b_r) {
    int tid = threadIdx.x;
    for (int idx = tid; idx < 256 * HID; idx += blockDim.x) {
        int k = idx >> 7;
        int n = idx & 127;
        g_Wcat[idx] = (k < HID) ? W_l[k * HID + n] : W_r[(k - HID) * HID + n];
    }
    if (tid < HID) g_bsum[tid] = b_l[tid] + b_r[tid];
}

// C[M,128] = tanh(A[M,K] @ W[K,128] + bias)
// 256 threads, CTA tile 64 x 128, thread tile 8 rows x 4 cols (float4).
// Weights fully resident in smem; A tile staged in smem.
template <int K>
__global__ void __launch_bounds__(256) gemm_tanh(const float* __restrict__ A,
                                                 const float* __restrict__ W,
                                                 const float* __restrict__ bias,
                                                 float* __restrict__ C, int M) {
    extern __shared__ float smem[];
    float* sW = smem;             // K * 128 floats
    float* sA = smem + K * HID;   // 64 * K floats

    const int tid = threadIdx.x;
    const int m0  = blockIdx.x * 64;

    // Stage weights (K*128 floats, float4 vectorized, coalesced).
    {
        const float4* Wg  = (const float4*)W;
        float4*       sW4 = (float4*)sW;
        const int n4 = (K * HID) / 4;
        #pragma unroll 4
        for (int i = tid; i < n4; i += 256) sW4[i] = Wg[i];
    }
    // Stage A tile (only valid rows; K is a multiple of 4 so rows*K/4 is exact).
    {
        int rows = M - m0;
        if (rows > 64) rows = 64;
        const float4* Ag  = (const float4*)(A + (size_t)m0 * K);
        float4*       sA4 = (float4*)sA;
        const int v4 = rows * (K / 4);
        #pragma unroll 4
        for (int i = tid; i < v4; i += 256) sA4[i] = Ag[i];
    }
    __syncthreads();

    const int c  = tid & 31;         // column group: cols 4c..4c+3
    const int rb = (tid >> 5) * 8;   // row base within tile

    float4 acc[8];
    #pragma unroll
    for (int r = 0; r < 8; r++) acc[r] = make_float4(0.f, 0.f, 0.f, 0.f);

    const float4* sW4 = (const float4*)sW;
    #pragma unroll 4
    for (int k = 0; k < K; k++) {
        float4 w = sW4[k * 32 + c];             // consecutive float4 across lanes
        #pragma unroll
        for (int r = 0; r < 8; r++) {
            float a = sA[(rb + r) * K + k];     // same addr across warp -> broadcast
            acc[r].x = fmaf(a, w.x, acc[r].x);
            acc[r].y = fmaf(a, w.y, acc[r].y);
            acc[r].z = fmaf(a, w.z, acc[r].z);
            acc[r].w = fmaf(a, w.w, acc[r].w);
        }
    }

    float4 bv = ((const float4*)bias)[c];
    #pragma unroll
    for (int r = 0; r < 8; r++) {
        int row = m0 + rb + r;
        if (row < M) {
            float4 o;
            o.x = tanhf(acc[r].x + bv.x);
            o.y = tanhf(acc[r].y + bv.y);
            o.z = tanhf(acc[r].z + bv.z);
            o.w = tanhf(acc[r].w + bv.w);
            ((float4*)C)[(size_t)row * 32 + c] = o;
        }
    }
}

extern "C" void kernel_launch(void* const* d_in, const int* in_sizes, int n_in,
                              void* d_out, int out_size) {
    const float* leaf_x = (const float*)d_in[0];
    const float* W_in   = (const float*)d_in[1];
    const float* b_in   = (const float*)d_in[2];
    const float* W_l    = (const float*)d_in[3];
    const float* b_l    = (const float*)d_in[4];
    const float* W_r    = (const float*)d_in[5];
    const float* b_r    = (const float*)d_in[6];

    // Resolve device-global addresses (host-side, immediate, capture-safe).
    void *pA, *pB, *pW, *pb;
    cudaGetSymbolAddress(&pA, g_bufA);
    cudaGetSymbolAddress(&pB, g_bufB);
    cudaGetSymbolAddress(&pW, g_Wcat);
    cudaGetSymbolAddress(&pb, g_bsum);
    float* bufA = (float*)pA;
    float* bufB = (float*)pB;
    float* Wcat = (float*)pW;
    float* bsum = (float*)pb;

    // Dynamic smem opt-in (immediate host API, capture-safe; no static guards).
    const int smem_leaf  = (64 * HID + 64 * 64) * (int)sizeof(float);     //  48 KB
    const int smem_level = (256 * HID + 64 * 256) * (int)sizeof(float);   // 192 KB
    cudaFuncSetAttribute(gemm_tanh<64>,  cudaFuncAttributeMaxDynamicSharedMemorySize, smem_leaf);
    cudaFuncSetAttribute(gemm_tanh<256>, cudaFuncAttributeMaxDynamicSharedMemorySize, smem_level);

    prep_kernel<<<1, 256>>>(W_l, b_l, W_r, b_r);

    // Leaf level: H0 = tanh(leaf_x @ W_in + b_in)
    gemm_tanh<64><<<N_LEAVES / 64, 256, smem_leaf>>>(leaf_x, W_in, b_in, bufA, N_LEAVES);

    // 18 internal levels. reshape(H,[M/2,256]) @ vstack(W_l,W_r) + (b_l+b_r).
    float* cur = bufA;
    int M = N_LEAVES;
    for (int lvl = 0; lvl < 18; lvl++) {
        int Mo = M >> 1;
        float* out = (lvl == 17) ? (float*)d_out : ((lvl & 1) ? bufA : bufB);
        gemm_tanh<256><<<(Mo + 63) / 64, 256, smem_level>>>(cur, Wcat, bsum, out, Mo);
        cur = out;
        M = Mo;
    }
}